// round 15
// baseline (speedup 1.0000x reference)
#include <cuda_runtime.h>
#include <cuda_bf16.h>
#include <cstdint>
#include <cstring>

#define TS   512
#define BSZ  256
#define DIN  256
#define HID  256
#define OUTD 64
#define MROWS (TS * BSZ)
#define PAK  40              // xw_mma staged tile pitch in bf16

// xw_mma smem layout (bytes)
#define OFF_BIAS 0
#define OFF_AH   1024
#define OFF_AL   (OFF_AH + 128 * PAK * 2)
#define OFF_BH   (OFF_AL + 128 * PAK * 2)
#define OFF_BL   (OFF_BH + 128 * PAK * 2)
#define SMEM_MMA (OFF_BL + 128 * PAK * 2)      // 41984 B

// serial smem (bytes). Pitch 144B holds one 64-entry bf16 k-chunk (+16 pad).
// A: 2 buffers x [2 planes][4 ck][32 rows][144]  = 2 x 36864 = 73728
// W: [2 planes][4 ck][128 n][144]                = 147456
#define A_CK    4608               // 32*144
#define A_PLANE 18432              // 4*A_CK
#define A_BUFSZ 36864              // 2*A_PLANE
#define W_BASE  73728
#define W_CK    18432              // 128*144
#define W_PLANE 73728              // 4*W_CK
#define SMEM_SER (W_BASE + 2 * W_PLANE)   // 221184 B

extern __shared__ char smem_dyn[];

__device__ float          g_xwb[(size_t)MROWS * 1024];   // x@Wx + b, [m][g*256+j]
__device__ __nv_bfloat16  g_ah[(size_t)MROWS * DIN];
__device__ __nv_bfloat16  g_al[(size_t)MROWS * DIN];
__device__ __nv_bfloat16  g_wth[1024 * 256];              // W^T hi [n][k]
__device__ __nv_bfloat16  g_wtl[1024 * 256];              // W^T lo

__device__ __forceinline__ float sigmoidf_(float x) { return 1.0f / (1.0f + __expf(-x)); }
__device__ __forceinline__ float tanhf_(float x) {
    float e = __expf(2.0f * x); return 1.0f - 2.0f / (e + 1.0f);
}
__device__ __forceinline__ uint32_t s2u(const void* p) {
    uint32_t a; asm("{ .reg .u64 t; cvta.to.shared.u64 t, %1; cvt.u32.u64 %0, t; }" : "=r"(a) : "l"(p));
    return a;
}
__device__ __forceinline__ uint32_t pack2(float a, float b) {
    __nv_bfloat162 t; t.x = __float2bfloat16(a); t.y = __float2bfloat16(b);
    uint32_t r; memcpy(&r, &t, 4); return r;
}
__device__ __forceinline__ float rebf(float v) {
    return __bfloat162float(__float2bfloat16(v));
}
__device__ __forceinline__ uint32_t cluster_rank() {
    uint32_t r; asm("mov.u32 %0, %%cluster_ctarank;" : "=r"(r)); return r;
}
__device__ __forceinline__ uint32_t mapa_u32(uint32_t addr, uint32_t rank) {
    uint32_t d; asm("mapa.shared::cluster.u32 %0, %1, %2;" : "=r"(d) : "r"(addr), "r"(rank));
    return d;
}
__device__ __forceinline__ void st_cluster(uint32_t addr, uint32_t val) {
    asm volatile("st.shared::cluster.u32 [%0], %1;" :: "r"(addr), "r"(val) : "memory");
}
#define CLUSTER_SYNC() do { \
    asm volatile("barrier.cluster.arrive.aligned;" ::: "memory"); \
    asm volatile("barrier.cluster.wait.aligned;" ::: "memory"); \
} while (0)

#define LDSM4(d0, d1, d2, d3, addr) \
    asm volatile("ldmatrix.sync.aligned.m8n8.x4.shared.b16 {%0,%1,%2,%3}, [%4];" \
                 : "=r"(d0), "=r"(d1), "=r"(d2), "=r"(d3) : "r"(addr))

#define MMA16816(c, a, b0, b1) \
    asm volatile("mma.sync.aligned.m16n8k16.row.col.f32.bf16.bf16.f32 " \
                 "{%0,%1,%2,%3}, {%4,%5,%6,%7}, {%8,%9}, {%0,%1,%2,%3};" \
                 : "+f"((c)[0]), "+f"((c)[1]), "+f"((c)[2]), "+f"((c)[3]) \
                 : "r"((a)[0]), "r"((a)[1]), "r"((a)[2]), "r"((a)[3]), "r"(b0), "r"(b1))

// ---------------- conversions ----------------
__global__ void convert_x(const float* __restrict__ x) {
    size_t i = (size_t)blockIdx.x * 256 + threadIdx.x;
    float4 v = ((const float4*)x)[i];
    uint2 ph, pl;
    ph.x = pack2(v.x, v.y); ph.y = pack2(v.z, v.w);
    pl.x = pack2(v.x - rebf(v.x), v.y - rebf(v.y));
    pl.y = pack2(v.z - rebf(v.z), v.w - rebf(v.w));
    ((uint2*)g_ah)[i] = ph;
    ((uint2*)g_al)[i] = pl;
}

__global__ void convert_w(const float* __restrict__ Wf, const float* __restrict__ Wi,
                          const float* __restrict__ Wc, const float* __restrict__ Wo) {
    int n = blockIdx.x, k = threadIdx.x;
    int g = n >> 8, j = n & 255;
    const float* Wg = (g == 0) ? Wf : (g == 1) ? Wi : (g == 2) ? Wc : Wo;
    float v = Wg[(size_t)k * HID + j];
    g_wth[n * 256 + k] = __float2bfloat16(v);
    g_wtl[n * 256 + k] = __float2bfloat16(v - rebf(v));
}

// ---------------- xwb = x @ Wx + b via mma.sync bf16 3-term split ----------------
__global__ void __launch_bounds__(256) xw_mma(
    const float* __restrict__ bfp, const float* __restrict__ bip,
    const float* __restrict__ bcp, const float* __restrict__ bop)
{
    char* sm = smem_dyn;
    float* sBias = (float*)(sm + OFF_BIAS);
    const uint32_t uAh = s2u(sm + OFF_AH);
    const uint32_t uAl = s2u(sm + OFF_AL);
    const uint32_t uBh = s2u(sm + OFF_BH);
    const uint32_t uBl = s2u(sm + OFF_BL);

    const int tid  = threadIdx.x;
    const int w    = tid >> 5;
    const int lane = tid & 31;
    const int wm   = w & 3;
    const int wn   = w >> 2;
    const int n0   = blockIdx.x * 128;
    const int m0   = blockIdx.y * 128;

    if (tid < 128) {
        int g = n0 >> 8;
        const float* bg = (g == 0) ? bfp : (g == 1) ? bip : (g == 2) ? bcp : bop;
        sBias[tid] = bg[(n0 & 255) + tid];
    }

    const int arow  = lane & 15;
    const int ahalf = (lane >> 4) & 1;
    const int brow  = ((lane >> 4) & 1) * 8 + (lane & 7);
    const int bcol  = ((lane >> 3) & 1) * 8;

    float c[2][8][4];
    #pragma unroll
    for (int mt = 0; mt < 2; ++mt)
        #pragma unroll
        for (int nt = 0; nt < 8; ++nt)
            #pragma unroll
            for (int q = 0; q < 4; ++q) c[mt][nt][q] = 0.f;

    for (int ck = 0; ck < 8; ++ck) {
        const int k0 = ck * 32;
        __syncthreads();
        #pragma unroll
        for (int it = 0; it < 2; ++it) {
            int idx = tid + it * 256;
            int r = idx >> 2, cq = idx & 3;
            uint32_t doff = (uint32_t)(r * (PAK * 2) + cq * 16);
            *(uint4*)(sm + OFF_AH + doff) = *(const uint4*)(g_ah  + (size_t)(m0 + r) * 256 + k0 + cq * 8);
            *(uint4*)(sm + OFF_AL + doff) = *(const uint4*)(g_al  + (size_t)(m0 + r) * 256 + k0 + cq * 8);
            *(uint4*)(sm + OFF_BH + doff) = *(const uint4*)(g_wth + (size_t)(n0 + r) * 256 + k0 + cq * 8);
            *(uint4*)(sm + OFF_BL + doff) = *(const uint4*)(g_wtl + (size_t)(n0 + r) * 256 + k0 + cq * 8);
        }
        __syncthreads();

        #pragma unroll
        for (int ks = 0; ks < 2; ++ks) {
            const int kk = ks * 16;
            uint32_t ah[2][4], al[2][4];
            #pragma unroll
            for (int mt = 0; mt < 2; ++mt) {
                uint32_t ao = (uint32_t)((wm * 32 + mt * 16 + arow) * (PAK * 2) + (kk + ahalf * 8) * 2);
                LDSM4(ah[mt][0], ah[mt][1], ah[mt][2], ah[mt][3], uAh + ao);
                LDSM4(al[mt][0], al[mt][1], al[mt][2], al[mt][3], uAl + ao);
            }
            #pragma unroll
            for (int np = 0; np < 4; ++np) {
                uint32_t bo = (uint32_t)((wn * 64 + np * 16 + brow) * (PAK * 2) + (kk + bcol) * 2);
                uint32_t bh[4], bl[4];
                LDSM4(bh[0], bh[1], bh[2], bh[3], uBh + bo);
                LDSM4(bl[0], bl[1], bl[2], bl[3], uBl + bo);
                #pragma unroll
                for (int mt = 0; mt < 2; ++mt) {
                    MMA16816(c[mt][2 * np],     ah[mt], bh[0], bh[1]);
                    MMA16816(c[mt][2 * np + 1], ah[mt], bh[2], bh[3]);
                    MMA16816(c[mt][2 * np],     ah[mt], bl[0], bl[1]);
                    MMA16816(c[mt][2 * np + 1], ah[mt], bl[2], bl[3]);
                    MMA16816(c[mt][2 * np],     al[mt], bh[0], bh[1]);
                    MMA16816(c[mt][2 * np + 1], al[mt], bh[2], bh[3]);
                }
            }
        }
    }

    const int g  = lane >> 2;
    const int tg = lane & 3;
    float* base = g_xwb + (size_t)(m0 + wm * 32) * 1024 + n0 + wn * 64;
    #pragma unroll
    for (int mt = 0; mt < 2; ++mt) {
        #pragma unroll
        for (int nt = 0; nt < 8; ++nt) {
            float2 bv = *(float2*)&sBias[wn * 64 + nt * 8 + 2 * tg];
            float2 v0, v1;
            v0.x = c[mt][nt][0] + bv.x; v0.y = c[mt][nt][1] + bv.y;
            v1.x = c[mt][nt][2] + bv.x; v1.y = c[mt][nt][3] + bv.y;
            *(float2*)(base + (size_t)(mt * 16 + g)     * 1024 + nt * 8 + 2 * tg) = v0;
            *(float2*)(base + (size_t)(mt * 16 + g + 8) * 1024 + nt * 8 + 2 * tg) = v1;
        }
    }
}

// ---------------- serial loop: 8-CTA cluster per 32-row group, DSMEM h exchange ----------------
// 64 CTAs = 8 clusters. CTA rank owns hcols [rank*32, rank*32+32) (N=128 gate cols).
// Warp (mt = w>>2, wn = w&3): m16 x n32, full K=256. W columns gate-interleaved:
// n = wn*32 + g*8 + q  (hcol = wn*8+q) -> c[g] holds gate g of the thread's own cells.
__global__ void __launch_bounds__(256, 1) __cluster_dims__(8, 1, 1) lstm_serial(
    const int* __restrict__ lengths,
    const float* __restrict__ Wf, const float* __restrict__ Wi,
    const float* __restrict__ Wc, const float* __restrict__ Wo,
    const float* __restrict__ Wy, const float* __restrict__ by,
    float* __restrict__ out)
{
    char* sm = smem_dyn;
    const uint32_t uBase = s2u(sm);

    const int tid  = threadIdx.x;
    const int w    = tid >> 5;
    const int lane = tid & 31;
    const int mt   = w >> 2;
    const int wn   = w & 3;
    const int rank = (int)cluster_rank();
    const int grp  = blockIdx.x >> 3;
    const int b0   = grp * 32;

    // peer smem base addresses (all 8 cluster CTAs)
    uint32_t peer[8];
    #pragma unroll
    for (int r = 0; r < 8; ++r) peer[r] = mapa_u32(uBase, (uint32_t)r);

    // ---- zero A buffers (both), stage W hi/lo gate-interleaved ----
    for (int i = tid; i < 2 * A_BUFSZ / 4; i += 256) ((uint32_t*)sm)[i] = 0u;
    for (int i = tid; i < 128 * 256; i += 256) {
        int n = i & 127, k = i >> 7;
        int wnb = n >> 5, l = n & 31, g = l >> 3, q = l & 7;
        int j = rank * 32 + wnb * 8 + q;
        const float* __restrict__ Wg = (g == 0) ? Wf : (g == 1) ? Wi : (g == 2) ? Wc : Wo;
        float v = Wg[(size_t)(DIN + k) * HID + j];
        int ck = k >> 6, kk = k & 63;
        uint32_t off = (uint32_t)(W_BASE + ck * W_CK + n * 144 + kk * 2);
        *(__nv_bfloat16*)(sm + off)           = __float2bfloat16(v);
        *(__nv_bfloat16*)(sm + off + W_PLANE) = __float2bfloat16(v - rebf(v));
    }

    // thread cell ownership: rows rA, rB (local), cols jcl, jcl+1
    const int gl   = lane >> 2;
    const int tg   = lane & 3;
    const int rA   = mt * 16 + gl;
    const int rB   = rA + 8;
    const int jcl  = wn * 8 + 2 * tg;            // local hcol
    const int jg   = rank * 32 + jcl;            // global hcol
    const int lenA = lengths[b0 + rA];
    const int lenB = lengths[b0 + rB];
    float cs[4] = {0.f, 0.f, 0.f, 0.f};
    uint32_t hpAhi = 0u, hpAlo = 0u, hpBhi = 0u, hpBlo = 0u;

    // DSMEM write offsets (cells live in k-chunk ck = jg>>6 of peers' A buffers)
    const int ckA = jg >> 6, kkA = jg & 63;
    const uint32_t offA = (uint32_t)(ckA * A_CK + rA * 144 + kkA * 2);   // + nb*A_BUFSZ (+A_PLANE for lo)

    // MMA fragment addressing
    const int arow  = lane & 15;
    const int ahalf = (lane >> 4) & 1;
    const int brow  = ((lane >> 4) & 1) * 8 + (lane & 7);
    const int bcol  = ((lane >> 3) & 1) * 8;

    // xwb prefetch t=0
    const float* xrA = g_xwb + ((size_t)(b0 + rA)) * 1024 + jg;
    const float* xrB = g_xwb + ((size_t)(b0 + rB)) * 1024 + jg;
    float2 pfA = __ldcg((const float2*)xrA), piA = __ldcg((const float2*)(xrA + 256));
    float2 pcA = __ldcg((const float2*)(xrA + 512)), poA = __ldcg((const float2*)(xrA + 768));
    float2 pfB = __ldcg((const float2*)xrB), piB = __ldcg((const float2*)(xrB + 256));
    float2 pcB = __ldcg((const float2*)(xrB + 512)), poB = __ldcg((const float2*)(xrB + 768));

    __syncthreads();
    CLUSTER_SYNC();

    for (int t = 0; t < TS; ++t) {
        const uint32_t aBuf = uBase + (uint32_t)((t & 1) * A_BUFSZ);

        // ---- MMA: full K=256, 3-term split; c[g] = gate g ----
        float c[4][4];
        #pragma unroll
        for (int g = 0; g < 4; ++g) { c[g][0] = 0.f; c[g][1] = 0.f; c[g][2] = 0.f; c[g][3] = 0.f; }
        #pragma unroll
        for (int ck = 0; ck < 4; ++ck) {
            #pragma unroll
            for (int ks = 0; ks < 4; ++ks) {
                const int kk = ks * 16;
                uint32_t ah[4], al[4], bh0[4], bh1[4], bl0[4], bl1[4];
                uint32_t ao = aBuf + (uint32_t)(ck * A_CK + (mt * 16 + arow) * 144 + (kk + ahalf * 8) * 2);
                LDSM4(ah[0], ah[1], ah[2], ah[3], ao);
                LDSM4(al[0], al[1], al[2], al[3], ao + A_PLANE);
                uint32_t bo = uBase + (uint32_t)(W_BASE + ck * W_CK + (wn * 32 + brow) * 144 + (kk + bcol) * 2);
                LDSM4(bh0[0], bh0[1], bh0[2], bh0[3], bo);
                LDSM4(bh1[0], bh1[1], bh1[2], bh1[3], bo + 16 * 144);
                LDSM4(bl0[0], bl0[1], bl0[2], bl0[3], bo + W_PLANE);
                LDSM4(bl1[0], bl1[1], bl1[2], bl1[3], bo + W_PLANE + 16 * 144);
                MMA16816(c[0], ah, bh0[0], bh0[1]);
                MMA16816(c[1], ah, bh0[2], bh0[3]);
                MMA16816(c[2], ah, bh1[0], bh1[1]);
                MMA16816(c[3], ah, bh1[2], bh1[3]);
                MMA16816(c[0], ah, bl0[0], bl0[1]);
                MMA16816(c[1], ah, bl0[2], bl0[3]);
                MMA16816(c[2], ah, bl1[0], bl1[1]);
                MMA16816(c[3], ah, bl1[2], bl1[3]);
                MMA16816(c[0], al, bh0[0], bh0[1]);
                MMA16816(c[1], al, bh0[2], bh0[3]);
                MMA16816(c[2], al, bh1[0], bh1[1]);
                MMA16816(c[3], al, bh1[2], bh1[3]);
            }
        }

        // ---- thread-local epilogue (c[0]=f, c[1]=i, c[2]=c~, c[3]=o) ----
        {
            float f0 = sigmoidf_(c[0][0] + pfA.x), f1 = sigmoidf_(c[0][1] + pfA.y);
            float i0 = sigmoidf_(c[1][0] + piA.x), i1 = sigmoidf_(c[1][1] + piA.y);
            float q0 = tanhf_(c[2][0] + pcA.x),    q1 = tanhf_(c[2][1] + pcA.y);
            float o0 = sigmoidf_(c[3][0] + poA.x), o1 = sigmoidf_(c[3][1] + poA.y);
            float cn0 = f0 * cs[0] + i0 * q0;
            float cn1 = f1 * cs[1] + i1 * q1;
            float hn0 = o0 * tanhf_(cn0);
            float hn1 = o1 * tanhf_(cn1);
            if (t < lenA) {
                cs[0] = cn0; cs[1] = cn1;
                hpAhi = pack2(hn0, hn1);
                hpAlo = pack2(hn0 - rebf(hn0), hn1 - rebf(hn1));
            }
            f0 = sigmoidf_(c[0][2] + pfB.x); f1 = sigmoidf_(c[0][3] + pfB.y);
            i0 = sigmoidf_(c[1][2] + piB.x); i1 = sigmoidf_(c[1][3] + piB.y);
            q0 = tanhf_(c[2][2] + pcB.x);    q1 = tanhf_(c[2][3] + pcB.y);
            o0 = sigmoidf_(c[3][2] + poB.x); o1 = sigmoidf_(c[3][3] + poB.y);
            cn0 = f0 * cs[2] + i0 * q0;
            cn1 = f1 * cs[3] + i1 * q1;
            hn0 = o0 * tanhf_(cn0);
            hn1 = o1 * tanhf_(cn1);
            if (t < lenB) {
                cs[2] = cn0; cs[3] = cn1;
                hpBhi = pack2(hn0, hn1);
                hpBlo = pack2(hn0 - rebf(hn0), hn1 - rebf(hn1));
            }
        }

        // ---- DSMEM multicast publish into all 8 CTAs' next A buffer ----
        {
            const uint32_t nbOff = (uint32_t)(((t + 1) & 1) * A_BUFSZ) + offA;
            #pragma unroll
            for (int r = 0; r < 8; ++r) {
                uint32_t pb = peer[r] + nbOff;
                st_cluster(pb,                    hpAhi);
                st_cluster(pb + A_PLANE,          hpAlo);
                st_cluster(pb + 8 * 144,          hpBhi);
                st_cluster(pb + 8 * 144 + A_PLANE, hpBlo);
            }
        }

        // ---- prefetch next xwb (hidden under cluster wait) ----
        if (t + 1 < TS) {
            const float* xA = g_xwb + ((size_t)(t + 1) * BSZ + b0 + rA) * 1024 + jg;
            const float* xB = g_xwb + ((size_t)(t + 1) * BSZ + b0 + rB) * 1024 + jg;
            pfA = __ldcg((const float2*)xA); piA = __ldcg((const float2*)(xA + 256));
            pcA = __ldcg((const float2*)(xA + 512)); poA = __ldcg((const float2*)(xA + 768));
            pfB = __ldcg((const float2*)xB); piB = __ldcg((const float2*)(xB + 256));
            pcB = __ldcg((const float2*)(xB + 512)); poB = __ldcg((const float2*)(xB + 768));
        }

        CLUSTER_SYNC();
    }

    // ---- emit final h (fp32) directly from registers ----
    {
        float hA0 = __uint_as_float(hpAhi << 16) + __uint_as_float(hpAlo << 16);
        float hA1 = __uint_as_float(hpAhi & 0xFFFF0000u) + __uint_as_float(hpAlo & 0xFFFF0000u);
        float hB0 = __uint_as_float(hpBhi << 16) + __uint_as_float(hpBlo << 16);
        float hB1 = __uint_as_float(hpBhi & 0xFFFF0000u) + __uint_as_float(hpBlo & 0xFFFF0000u);
        *(float2*)(out + BSZ * OUTD + (size_t)(b0 + rA) * HID + jg) = make_float2(hA0, hA1);
        *(float2*)(out + BSZ * OUTD + (size_t)(b0 + rB) * HID + jg) = make_float2(hB0, hB1);
    }

    // ---- y = h @ Wy + by from cluster-local h (A buffer 0) ----
    float* wyS = (float*)(sm + W_BASE);
    for (int i = tid; i < HID * OUTD; i += 256) wyS[i] = Wy[i];
    __syncthreads();
    {
        const int r   = tid >> 3;          // row 0..31
        const int ocb = (tid & 7) * 8;     // 8 out cols
        float acc[8];
        #pragma unroll
        for (int o = 0; o < 8; ++o) acc[o] = by[ocb + o];
        #pragma unroll 4
        for (int k2 = 0; k2 < 128; ++k2) {
            int k = k2 * 2, ck = k >> 6, kk = k & 63;
            uint32_t hw = *(const uint32_t*)(sm + ck * A_CK + r * 144 + kk * 2);
            uint32_t lw = *(const uint32_t*)(sm + A_PLANE + ck * A_CK + r * 144 + kk * 2);
            float h0 = __uint_as_float(hw << 16) + __uint_as_float(lw << 16);
            float h1 = __uint_as_float(hw & 0xFFFF0000u) + __uint_as_float(lw & 0xFFFF0000u);
            const float* w0 = wyS + k * OUTD + ocb;
            #pragma unroll
            for (int o = 0; o < 8; ++o)
                acc[o] += h0 * w0[o] + h1 * w0[OUTD + o];
        }
        float* yo = out + (size_t)(b0 + r) * OUTD + ocb;
        *(float4*)(yo)     = make_float4(acc[0], acc[1], acc[2], acc[3]);
        *(float4*)(yo + 4) = make_float4(acc[4], acc[5], acc[6], acc[7]);
    }
}

extern "C" void kernel_launch(void* const* d_in, const int* in_sizes, int n_in,
                              void* d_out, int out_size) {
    const float* x       = (const float*)d_in[0];
    const int*   lengths = (const int*)  d_in[1];
    const float* Wf = (const float*)d_in[2];  const float* bf = (const float*)d_in[3];
    const float* Wi = (const float*)d_in[4];  const float* bi = (const float*)d_in[5];
    const float* Wc = (const float*)d_in[6];  const float* bc = (const float*)d_in[7];
    const float* Wo = (const float*)d_in[8];  const float* bo = (const float*)d_in[9];
    const float* Wy = (const float*)d_in[10]; const float* by = (const float*)d_in[11];
    float* out = (float*)d_out;

    cudaFuncSetAttribute(xw_mma, cudaFuncAttributeMaxDynamicSharedMemorySize, SMEM_MMA);
    cudaFuncSetAttribute(lstm_serial, cudaFuncAttributeMaxDynamicSharedMemorySize, SMEM_SER);

    convert_x<<<(MROWS * DIN / 4) / 256, 256>>>(x);
    convert_w<<<1024, 256>>>(Wf, Wi, Wc, Wo);
    xw_mma<<<dim3(8, MROWS / 128), 256, SMEM_MMA>>>(bf, bi, bc, bo);
    lstm_serial<<<64, 256, SMEM_SER>>>(lengths, Wf, Wi, Wc, Wo, Wy, by, out);
}

// round 16
// speedup vs baseline: 1.3036x; 1.3036x over previous
#include <cuda_runtime.h>
#include <cuda_bf16.h>
#include <cstdint>
#include <cstring>

#define TS   512
#define BSZ  256
#define DIN  256
#define HID  256
#define OUTD 64
#define MROWS (TS * BSZ)
#define NCTA_S 256           // serial: 16 row-groups x 16 col-CTAs, 2 CTAs/SM
#define PAK  40              // staged tile pitch in bf16 (80B rows: ldmatrix conflict-free)

// xw_mma smem layout (bytes)
#define OFF_BIAS 0
#define OFF_AH   1024
#define OFF_AL   (OFF_AH + 128 * PAK * 2)
#define OFF_BH   (OFF_AL + 128 * PAK * 2)
#define OFF_BL   (OFF_BH + 128 * PAK * 2)
#define SMEM_MMA (OFF_BL + 128 * PAK * 2)      // 41984 B

// serial smem (bytes): A 16r x 256k hi/lo (pitch 80B, 8 k-chunks), W 64n x 256k hi/lo
#define S_AH  0
#define S_AL  10240            // 8 * 16*80
#define S_WH  20480
#define S_WL  (S_WH + 40960)   // 8 * 64*80 each
#define SMEM_SER (S_WL + 40960)   // 102400 B  -> 2 CTAs/SM

extern __shared__ char smem_dyn[];

__device__ float          g_xwb[(size_t)MROWS * 1024];   // x@Wx + b, [m][g*256+j]
__device__ __nv_bfloat16  g_ah[(size_t)MROWS * DIN];
__device__ __nv_bfloat16  g_al[(size_t)MROWS * DIN];
__device__ __nv_bfloat16  g_wth[1024 * 256];              // W^T hi [n][k]
__device__ __nv_bfloat16  g_wtl[1024 * 256];              // W^T lo
__device__ uint32_t       g_hpk[2][BSZ * HID];            // h packed: hi bf16 <<16 | lo bf16
__device__ unsigned       g_rbar[16][64];                 // per-row-group barriers (256B apart)
__device__ unsigned       g_bar;                          // final global barrier

__device__ __forceinline__ float sigmoidf_(float x) { return 1.0f / (1.0f + __expf(-x)); }
__device__ __forceinline__ float tanhf_(float x) {
    float e = __expf(2.0f * x); return 1.0f - 2.0f / (e + 1.0f);
}
__device__ __forceinline__ uint32_t s2u(const void* p) {
    uint32_t a; asm("{ .reg .u64 t; cvta.to.shared.u64 t, %1; cvt.u32.u64 %0, t; }" : "=r"(a) : "l"(p));
    return a;
}
__device__ __forceinline__ uint32_t pack2(float a, float b) {
    __nv_bfloat162 t; t.x = __float2bfloat16(a); t.y = __float2bfloat16(b);
    uint32_t r; memcpy(&r, &t, 4); return r;
}
__device__ __forceinline__ float rebf(float v) {
    return __bfloat162float(__float2bfloat16(v));
}
__device__ __forceinline__ uint32_t packsplit(float v) {
    __nv_bfloat16 hb = __float2bfloat16(v);
    unsigned short hu; memcpy(&hu, &hb, 2);
    float hf = __uint_as_float((uint32_t)hu << 16);
    __nv_bfloat16 lb = __float2bfloat16(v - hf);
    unsigned short lu; memcpy(&lu, &lb, 2);
    return ((uint32_t)hu << 16) | (uint32_t)lu;
}
__device__ __forceinline__ float unpacksplit(uint32_t u) {
    return __uint_as_float(u & 0xFFFF0000u) + __uint_as_float(u << 16);
}
__device__ __forceinline__ void arrive_release(unsigned* ctr) {
    asm volatile("red.release.gpu.global.add.u32 [%0], %1;" :: "l"(ctr), "r"(1u) : "memory");
}
__device__ __forceinline__ void wait_target(const unsigned* ctr, unsigned tgt) {
    unsigned v;
    do {
        asm volatile("ld.global.acquire.gpu.u32 %0, [%1];" : "=r"(v) : "l"(ctr));
        if (v >= tgt) break;
        __nanosleep(20);
    } while (true);
}

#define LDSM4(d0, d1, d2, d3, addr) \
    asm volatile("ldmatrix.sync.aligned.m8n8.x4.shared.b16 {%0,%1,%2,%3}, [%4];" \
                 : "=r"(d0), "=r"(d1), "=r"(d2), "=r"(d3) : "r"(addr))

#define MMA16816(c, a, b0, b1) \
    asm volatile("mma.sync.aligned.m16n8k16.row.col.f32.bf16.bf16.f32 " \
                 "{%0,%1,%2,%3}, {%4,%5,%6,%7}, {%8,%9}, {%0,%1,%2,%3};" \
                 : "+f"((c)[0]), "+f"((c)[1]), "+f"((c)[2]), "+f"((c)[3]) \
                 : "r"((a)[0]), "r"((a)[1]), "r"((a)[2]), "r"((a)[3]), "r"(b0), "r"(b1))

// ---------------- conversions ----------------
__global__ void convert_x(const float* __restrict__ x) {
    size_t i = (size_t)blockIdx.x * 256 + threadIdx.x;
    float4 v = ((const float4*)x)[i];
    uint2 ph, pl;
    ph.x = pack2(v.x, v.y); ph.y = pack2(v.z, v.w);
    pl.x = pack2(v.x - rebf(v.x), v.y - rebf(v.y));
    pl.y = pack2(v.z - rebf(v.z), v.w - rebf(v.w));
    ((uint2*)g_ah)[i] = ph;
    ((uint2*)g_al)[i] = pl;
}

__global__ void convert_w(const float* __restrict__ Wf, const float* __restrict__ Wi,
                          const float* __restrict__ Wc, const float* __restrict__ Wo) {
    int n = blockIdx.x, k = threadIdx.x;
    int g = n >> 8, j = n & 255;
    const float* Wg = (g == 0) ? Wf : (g == 1) ? Wi : (g == 2) ? Wc : Wo;
    float v = Wg[(size_t)k * HID + j];
    g_wth[n * 256 + k] = __float2bfloat16(v);
    g_wtl[n * 256 + k] = __float2bfloat16(v - rebf(v));
}

// ---------------- xwb = x @ Wx + b via mma.sync bf16 3-term split ----------------
__global__ void __launch_bounds__(256) xw_mma(
    const float* __restrict__ bfp, const float* __restrict__ bip,
    const float* __restrict__ bcp, const float* __restrict__ bop)
{
    char* sm = smem_dyn;
    float* sBias = (float*)(sm + OFF_BIAS);
    const uint32_t uAh = s2u(sm + OFF_AH);
    const uint32_t uAl = s2u(sm + OFF_AL);
    const uint32_t uBh = s2u(sm + OFF_BH);
    const uint32_t uBl = s2u(sm + OFF_BL);

    const int tid  = threadIdx.x;
    const int w    = tid >> 5;
    const int lane = tid & 31;
    const int wm   = w & 3;
    const int wn   = w >> 2;
    const int n0   = blockIdx.x * 128;
    const int m0   = blockIdx.y * 128;

    if (tid < 128) {
        int g = n0 >> 8;
        const float* bg = (g == 0) ? bfp : (g == 1) ? bip : (g == 2) ? bcp : bop;
        sBias[tid] = bg[(n0 & 255) + tid];
    }

    const int arow  = lane & 15;
    const int ahalf = (lane >> 4) & 1;
    const int brow  = ((lane >> 4) & 1) * 8 + (lane & 7);
    const int bcol  = ((lane >> 3) & 1) * 8;

    float c[2][8][4];
    #pragma unroll
    for (int mt = 0; mt < 2; ++mt)
        #pragma unroll
        for (int nt = 0; nt < 8; ++nt)
            #pragma unroll
            for (int q = 0; q < 4; ++q) c[mt][nt][q] = 0.f;

    for (int ck = 0; ck < 8; ++ck) {
        const int k0 = ck * 32;
        __syncthreads();
        #pragma unroll
        for (int it = 0; it < 2; ++it) {
            int idx = tid + it * 256;
            int r = idx >> 2, cq = idx & 3;
            uint32_t doff = (uint32_t)(r * (PAK * 2) + cq * 16);
            *(uint4*)(sm + OFF_AH + doff) = *(const uint4*)(g_ah  + (size_t)(m0 + r) * 256 + k0 + cq * 8);
            *(uint4*)(sm + OFF_AL + doff) = *(const uint4*)(g_al  + (size_t)(m0 + r) * 256 + k0 + cq * 8);
            *(uint4*)(sm + OFF_BH + doff) = *(const uint4*)(g_wth + (size_t)(n0 + r) * 256 + k0 + cq * 8);
            *(uint4*)(sm + OFF_BL + doff) = *(const uint4*)(g_wtl + (size_t)(n0 + r) * 256 + k0 + cq * 8);
        }
        __syncthreads();

        #pragma unroll
        for (int ks = 0; ks < 2; ++ks) {
            const int kk = ks * 16;
            uint32_t ah[2][4], al[2][4];
            #pragma unroll
            for (int mt = 0; mt < 2; ++mt) {
                uint32_t ao = (uint32_t)((wm * 32 + mt * 16 + arow) * (PAK * 2) + (kk + ahalf * 8) * 2);
                LDSM4(ah[mt][0], ah[mt][1], ah[mt][2], ah[mt][3], uAh + ao);
                LDSM4(al[mt][0], al[mt][1], al[mt][2], al[mt][3], uAl + ao);
            }
            #pragma unroll
            for (int np = 0; np < 4; ++np) {
                uint32_t bo = (uint32_t)((wn * 64 + np * 16 + brow) * (PAK * 2) + (kk + bcol) * 2);
                uint32_t bh[4], bl[4];
                LDSM4(bh[0], bh[1], bh[2], bh[3], uBh + bo);
                LDSM4(bl[0], bl[1], bl[2], bl[3], uBl + bo);
                #pragma unroll
                for (int mt = 0; mt < 2; ++mt) {
                    MMA16816(c[mt][2 * np],     ah[mt], bh[0], bh[1]);
                    MMA16816(c[mt][2 * np + 1], ah[mt], bh[2], bh[3]);
                    MMA16816(c[mt][2 * np],     ah[mt], bl[0], bl[1]);
                    MMA16816(c[mt][2 * np + 1], ah[mt], bl[2], bl[3]);
                    MMA16816(c[mt][2 * np],     al[mt], bh[0], bh[1]);
                    MMA16816(c[mt][2 * np + 1], al[mt], bh[2], bh[3]);
                }
            }
        }
    }

    const int g  = lane >> 2;
    const int tg = lane & 3;
    float* base = g_xwb + (size_t)(m0 + wm * 32) * 1024 + n0 + wn * 64;
    #pragma unroll
    for (int mt = 0; mt < 2; ++mt) {
        #pragma unroll
        for (int nt = 0; nt < 8; ++nt) {
            float2 bv = *(float2*)&sBias[wn * 64 + nt * 8 + 2 * tg];
            float2 v0, v1;
            v0.x = c[mt][nt][0] + bv.x; v0.y = c[mt][nt][1] + bv.y;
            v1.x = c[mt][nt][2] + bv.x; v1.y = c[mt][nt][3] + bv.y;
            *(float2*)(base + (size_t)(mt * 16 + g)     * 1024 + nt * 8 + 2 * tg) = v0;
            *(float2*)(base + (size_t)(mt * 16 + g + 8) * 1024 + nt * 8 + 2 * tg) = v1;
        }
    }
}

// ---------------- init ----------------
__global__ void init_state() {
    int i = blockIdx.x * blockDim.x + threadIdx.x;
    if (i == 0) g_bar = 0u;
    if (i < 16 * 64) ((unsigned*)g_rbar)[i] = 0u;
    if (i < BSZ * HID / 4) ((uint4*)g_hpk[0])[i] = make_uint4(0u, 0u, 0u, 0u);
}

// ---------------- serial loop: h @ Wh via mma.sync, 2 CTAs/SM ----------------
// 256 CTAs = 16 row-groups(16 rows) x 16 col-CTAs(16 hcols). 128 threads:
// 4 warps = m16 x 4*n16, full K=256 per warp, warp-local gate-shuffle epilogue.
// Sibling CTA on the same SM hides barrier/staging latency.
__global__ void __launch_bounds__(128, 2) lstm_serial(
    const int* __restrict__ lengths,
    const float* __restrict__ Wf, const float* __restrict__ Wi,
    const float* __restrict__ Wc, const float* __restrict__ Wo,
    const float* __restrict__ Wy, const float* __restrict__ by,
    float* __restrict__ out)
{
    char* sm = smem_dyn;
    const uint32_t uBase = s2u(sm);

    const int tid  = threadIdx.x;
    const int w    = tid >> 5;        // 0..3
    const int lane = tid & 31;
    const int nt   = w & 3;           // j-subblock (4 cols)
    const int bid  = blockIdx.x;
    const int grp  = bid >> 4;        // 16 groups of 16 rows
    const int b0   = grp * 16;
    const int j0   = (bid & 15) * 16;
    unsigned* myctr = &g_rbar[grp][0];

    // ---- stage W hi/lo once, gate-interleaved columns: n = nt*16 + g*4 + q ----
    for (int i = tid; i < 64 * 256; i += 128) {
        int n = i & 63, k = i >> 6;
        int ntb = n >> 4, l = n & 15, g = l >> 2, q = l & 3;
        int j = j0 + ntb * 4 + q;
        const float* __restrict__ Wg = (g == 0) ? Wf : (g == 1) ? Wi : (g == 2) ? Wc : Wo;
        float v = Wg[(size_t)(DIN + k) * HID + j];
        int ck = k >> 5, kk = k & 31;
        uint32_t off = (uint32_t)(ck * 5120 + n * 80 + kk * 2);
        *(__nv_bfloat16*)(sm + S_WH + off) = __float2bfloat16(v);
        *(__nv_bfloat16*)(sm + S_WL + off) = __float2bfloat16(v - rebf(v));
    }

    // lane cell ownership (after shuffle exchange)
    const int gl   = lane >> 2;
    const int tg   = lane & 3;
    const bool lowhalf = (tg < 2);
    const int rowL = gl + (lowhalf ? 0 : 8);      // 0..15
    const int rowG = b0 + rowL;
    const int jg   = j0 + nt * 4 + 2 * (tg & 1);
    const int len  = lengths[rowG];
    float2 cst = make_float2(0.f, 0.f);
    uint32_t hp0 = 0u, hp1 = 0u;

    // MMA fragment addressing
    const int arow  = lane & 15;
    const int ahalf = (lane >> 4) & 1;
    const int brow  = ((lane >> 4) & 1) * 8 + (lane & 7);
    const int bcol  = ((lane >> 3) & 1) * 8;

    // staging mapping: 128 threads cover 16 rows x 8 quads
    const int srow = tid >> 3;        // 0..15
    const int sqd  = tid & 7;
    const uint32_t sOffBase = (uint32_t)(srow * 80 + sqd * 8);

    // prefetch xwb for t=0
    const float* xr0 = g_xwb + ((size_t)rowG) * 1024 + jg;
    float2 pf = __ldcg((const float2*)xr0);
    float2 pi = __ldcg((const float2*)(xr0 + 256));
    float2 pc = __ldcg((const float2*)(xr0 + 512));
    float2 po = __ldcg((const float2*)(xr0 + 768));

    for (int t = 0; t < TS; ++t) {
        const uint32_t* __restrict__ hprev = g_hpk[t & 1];
        uint32_t*       __restrict__ hnext = g_hpk[(t + 1) & 1];

        // ---- issue all 8 staging loads (1 row x 8 k-chunks per thread) ----
        uint4 pA[8];
        {
            const uint32_t* hr = hprev + (size_t)(b0 + srow) * HID;
            #pragma unroll
            for (int it = 0; it < 8; ++it)
                pA[it] = __ldcg((const uint4*)(hr + (it * 8 + sqd) * 4));
        }

        // ---- store chunks 0..3 ----
        #pragma unroll
        for (int it = 0; it < 4; ++it) {
            uint4 p = pA[it];
            uint2 hi, lo;
            hi.x = __byte_perm(p.x, p.y, 0x7632);
            hi.y = __byte_perm(p.z, p.w, 0x7632);
            lo.x = __byte_perm(p.x, p.y, 0x5410);
            lo.y = __byte_perm(p.z, p.w, 0x5410);
            uint32_t off = (uint32_t)(it * 1280) + sOffBase;
            *(uint2*)(sm + S_AH + off) = hi;
            *(uint2*)(sm + S_AL + off) = lo;
        }
        __syncthreads();

        // ---- MMA chunks 0..3 ----
        float c0[4] = {0.f, 0.f, 0.f, 0.f};
        float c1[4] = {0.f, 0.f, 0.f, 0.f};
        #pragma unroll
        for (int ck = 0; ck < 4; ++ck) {
            #pragma unroll
            for (int ks = 0; ks < 2; ++ks) {
                const int kk = ks * 16;
                uint32_t ah[4], al[4], bh[4], bl[4];
                uint32_t ao = uBase + (uint32_t)(ck * 1280 + arow * 80 + (kk + ahalf * 8) * 2);
                LDSM4(ah[0], ah[1], ah[2], ah[3], ao + S_AH);
                LDSM4(al[0], al[1], al[2], al[3], ao + S_AL);
                uint32_t bo = uBase + (uint32_t)(ck * 5120 + (nt * 16 + brow) * 80 + (kk + bcol) * 2);
                LDSM4(bh[0], bh[1], bh[2], bh[3], bo + S_WH);
                LDSM4(bl[0], bl[1], bl[2], bl[3], bo + S_WL);
                MMA16816(c0, ah, bh[0], bh[1]);
                MMA16816(c1, ah, bh[2], bh[3]);
                MMA16816(c0, ah, bl[0], bl[1]);
                MMA16816(c1, ah, bl[2], bl[3]);
                MMA16816(c0, al, bh[0], bh[1]);
                MMA16816(c1, al, bh[2], bh[3]);
            }
        }

        // ---- store chunks 4..7 ----
        #pragma unroll
        for (int it = 4; it < 8; ++it) {
            uint4 p = pA[it];
            uint2 hi, lo;
            hi.x = __byte_perm(p.x, p.y, 0x7632);
            hi.y = __byte_perm(p.z, p.w, 0x7632);
            lo.x = __byte_perm(p.x, p.y, 0x5410);
            lo.y = __byte_perm(p.z, p.w, 0x5410);
            uint32_t off = (uint32_t)(it * 1280) + sOffBase;
            *(uint2*)(sm + S_AH + off) = hi;
            *(uint2*)(sm + S_AL + off) = lo;
        }
        __syncthreads();

        // ---- MMA chunks 4..7 ----
        #pragma unroll
        for (int ck = 4; ck < 8; ++ck) {
            #pragma unroll
            for (int ks = 0; ks < 2; ++ks) {
                const int kk = ks * 16;
                uint32_t ah[4], al[4], bh[4], bl[4];
                uint32_t ao = uBase + (uint32_t)(ck * 1280 + arow * 80 + (kk + ahalf * 8) * 2);
                LDSM4(ah[0], ah[1], ah[2], ah[3], ao + S_AH);
                LDSM4(al[0], al[1], al[2], al[3], ao + S_AL);
                uint32_t bo = uBase + (uint32_t)(ck * 5120 + (nt * 16 + brow) * 80 + (kk + bcol) * 2);
                LDSM4(bh[0], bh[1], bh[2], bh[3], bo + S_WH);
                LDSM4(bl[0], bl[1], bl[2], bl[3], bo + S_WL);
                MMA16816(c0, ah, bh[0], bh[1]);
                MMA16816(c1, ah, bh[2], bh[3]);
                MMA16816(c0, ah, bl[0], bl[1]);
                MMA16816(c1, ah, bl[2], bl[3]);
                MMA16816(c0, al, bh[0], bh[1]);
                MMA16816(c1, al, bh[2], bh[3]);
            }
        }

        // ---- warp-local gate exchange (shuffle xor 2) + epilogue ----
        {
            float s0 = lowhalf ? c0[2] : c0[0];
            float s1 = lowhalf ? c0[3] : c0[1];
            float s2 = lowhalf ? c1[2] : c1[0];
            float s3 = lowhalf ? c1[3] : c1[1];
            float e0 = __shfl_xor_sync(0xffffffffu, s0, 2);
            float e1 = __shfl_xor_sync(0xffffffffu, s1, 2);
            float e2 = __shfl_xor_sync(0xffffffffu, s2, 2);
            float e3 = __shfl_xor_sync(0xffffffffu, s3, 2);

            float f0, f1, i0, i1, q0, q1, o0, o1;
            if (lowhalf) {
                f0 = c0[0]; f1 = c0[1]; q0 = c1[0]; q1 = c1[1];
                i0 = e0;    i1 = e1;    o0 = e2;    o1 = e3;
            } else {
                i0 = c0[2]; i1 = c0[3]; o0 = c1[2]; o1 = c1[3];
                f0 = e0;    f1 = e1;    q0 = e2;    q1 = e3;
            }

            float fg0 = sigmoidf_(f0 + pf.x), fg1 = sigmoidf_(f1 + pf.y);
            float ig0 = sigmoidf_(i0 + pi.x), ig1 = sigmoidf_(i1 + pi.y);
            float ch0 = tanhf_(q0 + pc.x),    ch1 = tanhf_(q1 + pc.y);
            float og0 = sigmoidf_(o0 + po.x), og1 = sigmoidf_(o1 + po.y);
            float cn0 = fg0 * cst.x + ig0 * ch0;
            float cn1 = fg1 * cst.y + ig1 * ch1;
            float hn0 = og0 * tanhf_(cn0);
            float hn1 = og1 * tanhf_(cn1);
            if (t < len) {
                cst.x = cn0; cst.y = cn1;
                hp0 = packsplit(hn0); hp1 = packsplit(hn1);
            }
            uint2 hv; hv.x = hp0; hv.y = hp1;
            *(uint2*)(hnext + (size_t)rowG * HID + jg) = hv;
        }

        // ---- prefetch next-step xwb BEFORE barrier (hidden under wait) ----
        if (t + 1 < TS) {
            const float* xr = g_xwb + ((size_t)(t + 1) * BSZ + rowG) * 1024 + jg;
            pf = __ldcg((const float2*)xr);
            pi = __ldcg((const float2*)(xr + 256));
            pc = __ldcg((const float2*)(xr + 512));
            po = __ldcg((const float2*)(xr + 768));
        }

        // ---- row-group barrier (16 arrivals), single-thread nanosleep poll ----
        __syncthreads();
        if (tid == 0) {
            arrive_release(myctr);
            wait_target(myctr, 16u * (unsigned)(t + 1));
        }
        __syncthreads();
    }

    // global barrier before tail
    if (tid == 0) {
        arrive_release(&g_bar);
        wait_target(&g_bar, (unsigned)NCTA_S);
    }
    __syncthreads();

    // tail: y = h @ Wy + by (128 CTAs x 2 rows), then emit h (reconstructed fp32)
    const uint32_t* __restrict__ hfin = g_hpk[0];
    if (bid < 128) {
        const int row = bid * 2 + (tid >> 6);
        const int oc  = tid & 63;
        const uint32_t* hr = hfin + (size_t)row * HID;
        float acc = by[oc];
        #pragma unroll 4
        for (int k4 = 0; k4 < HID / 4; ++k4) {
            uint4 p = __ldcg((const uint4*)(hr + k4 * 4));
            const float* wp = Wy + (size_t)k4 * 4 * OUTD + oc;
            acc += unpacksplit(p.x) * wp[0] + unpacksplit(p.y) * wp[OUTD]
                 + unpacksplit(p.z) * wp[2 * OUTD] + unpacksplit(p.w) * wp[3 * OUTD];
        }
        out[(size_t)row * OUTD + oc] = acc;
    }
    {
        int idx = bid * 128 + tid;
        if (idx < BSZ * HID / 4) {
            uint4 p = __ldcg(((const uint4*)hfin) + idx);
            float4 v;
            v.x = unpacksplit(p.x); v.y = unpacksplit(p.y);
            v.z = unpacksplit(p.z); v.w = unpacksplit(p.w);
            ((float4*)(out + BSZ * OUTD))[idx] = v;
        }
    }
}

extern "C" void kernel_launch(void* const* d_in, const int* in_sizes, int n_in,
                              void* d_out, int out_size) {
    const float* x       = (const float*)d_in[0];
    const int*   lengths = (const int*)  d_in[1];
    const float* Wf = (const float*)d_in[2];  const float* bf = (const float*)d_in[3];
    const float* Wi = (const float*)d_in[4];  const float* bi = (const float*)d_in[5];
    const float* Wc = (const float*)d_in[6];  const float* bc = (const float*)d_in[7];
    const float* Wo = (const float*)d_in[8];  const float* bo = (const float*)d_in[9];
    const float* Wy = (const float*)d_in[10]; const float* by = (const float*)d_in[11];
    float* out = (float*)d_out;

    cudaFuncSetAttribute(xw_mma, cudaFuncAttributeMaxDynamicSharedMemorySize, SMEM_MMA);
    cudaFuncSetAttribute(lstm_serial, cudaFuncAttributeMaxDynamicSharedMemorySize, SMEM_SER);

    convert_x<<<(MROWS * DIN / 4) / 256, 256>>>(x);
    convert_w<<<1024, 256>>>(Wf, Wi, Wc, Wo);
    xw_mma<<<dim3(8, MROWS / 128), 256, SMEM_MMA>>>(bf, bi, bc, bo);
    init_state<<<64, 256>>>();
    lstm_serial<<<NCTA_S, 128, SMEM_SER>>>(lengths, Wf, Wi, Wc, Wo, Wy, by, out);
}

// round 17
// speedup vs baseline: 1.3525x; 1.0375x over previous
#include <cuda_runtime.h>
#include <cuda_bf16.h>
#include <cstdint>
#include <cstring>

#define TS   512
#define BSZ  256
#define DIN  256
#define HID  256
#define OUTD 64
#define MROWS (TS * BSZ)
#define NCTA_S 128           // serial: 16 row-groups(16 rows) x 8 col-CTAs(32 hcols)
#define PAK  40              // xw_mma staged tile pitch in bf16

// xw_mma smem layout (bytes)
#define OFF_BIAS 0
#define OFF_AH   1024
#define OFF_AL   (OFF_AH + 128 * PAK * 2)
#define OFF_BH   (OFF_AL + 128 * PAK * 2)
#define OFF_BL   (OFF_BH + 128 * PAK * 2)
#define SMEM_MMA (OFF_BL + 128 * PAK * 2)      // 41984 B

// serial smem (bytes):
// A: 2 buffers x { hi plane [8ck][16r][80B] , lo plane same } = 2 x 20480
// W: hi [8ck][128n][80B] = 81920 ; lo same
#define A_BUFSZ 20480
#define A_LO    10240
#define S_WH    40960
#define S_WL    122880
#define SMEM_SER 204800

extern __shared__ char smem_dyn[];

__device__ float          g_xwb[(size_t)MROWS * 1024];   // x@Wx + b, [m][g*256+j]
__device__ __nv_bfloat16  g_ah[(size_t)MROWS * DIN];
__device__ __nv_bfloat16  g_al[(size_t)MROWS * DIN];
__device__ __nv_bfloat16  g_wth[1024 * 256];              // W^T hi [n][k]
__device__ __nv_bfloat16  g_wtl[1024 * 256];              // W^T lo
__device__ uint32_t       g_hpk[2][BSZ * HID];            // h packed: hi bf16 <<16 | lo bf16
__device__ unsigned       g_rbar[16][64];                 // per-row-group barriers (256B apart)
__device__ unsigned       g_bar;                          // final global barrier

__device__ __forceinline__ float sigmoidf_(float x) { return 1.0f / (1.0f + __expf(-x)); }
__device__ __forceinline__ float tanhf_(float x) {
    float e = __expf(2.0f * x); return 1.0f - 2.0f / (e + 1.0f);
}
__device__ __forceinline__ uint32_t s2u(const void* p) {
    uint32_t a; asm("{ .reg .u64 t; cvta.to.shared.u64 t, %1; cvt.u32.u64 %0, t; }" : "=r"(a) : "l"(p));
    return a;
}
__device__ __forceinline__ uint32_t pack2(float a, float b) {
    __nv_bfloat162 t; t.x = __float2bfloat16(a); t.y = __float2bfloat16(b);
    uint32_t r; memcpy(&r, &t, 4); return r;
}
__device__ __forceinline__ float rebf(float v) {
    return __bfloat162float(__float2bfloat16(v));
}
__device__ __forceinline__ uint32_t packsplit(float v) {
    __nv_bfloat16 hb = __float2bfloat16(v);
    unsigned short hu; memcpy(&hu, &hb, 2);
    float hf = __uint_as_float((uint32_t)hu << 16);
    __nv_bfloat16 lb = __float2bfloat16(v - hf);
    unsigned short lu; memcpy(&lu, &lb, 2);
    return ((uint32_t)hu << 16) | (uint32_t)lu;
}
__device__ __forceinline__ float unpacksplit(uint32_t u) {
    return __uint_as_float(u & 0xFFFF0000u) + __uint_as_float(u << 16);
}
__device__ __forceinline__ void arrive_release(unsigned* ctr) {
    asm volatile("red.release.gpu.global.add.u32 [%0], %1;" :: "l"(ctr), "r"(1u) : "memory");
}
__device__ __forceinline__ void wait_target(const unsigned* ctr, unsigned tgt) {
    unsigned v; int spins = 0;
    do {
        asm volatile("ld.global.acquire.gpu.u32 %0, [%1];" : "=r"(v) : "l"(ctr));
        if (v >= tgt) break;
        if (++spins > 32) __nanosleep(32);
    } while (true);
}

#define LDSM4(d0, d1, d2, d3, addr) \
    asm volatile("ldmatrix.sync.aligned.m8n8.x4.shared.b16 {%0,%1,%2,%3}, [%4];" \
                 : "=r"(d0), "=r"(d1), "=r"(d2), "=r"(d3) : "r"(addr))

#define MMA16816(c, a, b0, b1) \
    asm volatile("mma.sync.aligned.m16n8k16.row.col.f32.bf16.bf16.f32 " \
                 "{%0,%1,%2,%3}, {%4,%5,%6,%7}, {%8,%9}, {%0,%1,%2,%3};" \
                 : "+f"((c)[0]), "+f"((c)[1]), "+f"((c)[2]), "+f"((c)[3]) \
                 : "r"((a)[0]), "r"((a)[1]), "r"((a)[2]), "r"((a)[3]), "r"(b0), "r"(b1))

// ---------------- conversions ----------------
__global__ void convert_x(const float* __restrict__ x) {
    size_t i = (size_t)blockIdx.x * 256 + threadIdx.x;
    float4 v = ((const float4*)x)[i];
    uint2 ph, pl;
    ph.x = pack2(v.x, v.y); ph.y = pack2(v.z, v.w);
    pl.x = pack2(v.x - rebf(v.x), v.y - rebf(v.y));
    pl.y = pack2(v.z - rebf(v.z), v.w - rebf(v.w));
    ((uint2*)g_ah)[i] = ph;
    ((uint2*)g_al)[i] = pl;
}

__global__ void convert_w(const float* __restrict__ Wf, const float* __restrict__ Wi,
                          const float* __restrict__ Wc, const float* __restrict__ Wo) {
    int n = blockIdx.x, k = threadIdx.x;
    int g = n >> 8, j = n & 255;
    const float* Wg = (g == 0) ? Wf : (g == 1) ? Wi : (g == 2) ? Wc : Wo;
    float v = Wg[(size_t)k * HID + j];
    g_wth[n * 256 + k] = __float2bfloat16(v);
    g_wtl[n * 256 + k] = __float2bfloat16(v - rebf(v));
}

// ---------------- xwb = x @ Wx + b via mma.sync bf16 3-term split ----------------
__global__ void __launch_bounds__(256) xw_mma(
    const float* __restrict__ bfp, const float* __restrict__ bip,
    const float* __restrict__ bcp, const float* __restrict__ bop)
{
    char* sm = smem_dyn;
    float* sBias = (float*)(sm + OFF_BIAS);
    const uint32_t uAh = s2u(sm + OFF_AH);
    const uint32_t uAl = s2u(sm + OFF_AL);
    const uint32_t uBh = s2u(sm + OFF_BH);
    const uint32_t uBl = s2u(sm + OFF_BL);

    const int tid  = threadIdx.x;
    const int w    = tid >> 5;
    const int lane = tid & 31;
    const int wm   = w & 3;
    const int wn   = w >> 2;
    const int n0   = blockIdx.x * 128;
    const int m0   = blockIdx.y * 128;

    if (tid < 128) {
        int g = n0 >> 8;
        const float* bg = (g == 0) ? bfp : (g == 1) ? bip : (g == 2) ? bcp : bop;
        sBias[tid] = bg[(n0 & 255) + tid];
    }

    const int arow  = lane & 15;
    const int ahalf = (lane >> 4) & 1;
    const int brow  = ((lane >> 4) & 1) * 8 + (lane & 7);
    const int bcol  = ((lane >> 3) & 1) * 8;

    float c[2][8][4];
    #pragma unroll
    for (int mt = 0; mt < 2; ++mt)
        #pragma unroll
        for (int nt = 0; nt < 8; ++nt)
            #pragma unroll
            for (int q = 0; q < 4; ++q) c[mt][nt][q] = 0.f;

    for (int ck = 0; ck < 8; ++ck) {
        const int k0 = ck * 32;
        __syncthreads();
        #pragma unroll
        for (int it = 0; it < 2; ++it) {
            int idx = tid + it * 256;
            int r = idx >> 2, cq = idx & 3;
            uint32_t doff = (uint32_t)(r * (PAK * 2) + cq * 16);
            *(uint4*)(sm + OFF_AH + doff) = *(const uint4*)(g_ah  + (size_t)(m0 + r) * 256 + k0 + cq * 8);
            *(uint4*)(sm + OFF_AL + doff) = *(const uint4*)(g_al  + (size_t)(m0 + r) * 256 + k0 + cq * 8);
            *(uint4*)(sm + OFF_BH + doff) = *(const uint4*)(g_wth + (size_t)(n0 + r) * 256 + k0 + cq * 8);
            *(uint4*)(sm + OFF_BL + doff) = *(const uint4*)(g_wtl + (size_t)(n0 + r) * 256 + k0 + cq * 8);
        }
        __syncthreads();

        #pragma unroll
        for (int ks = 0; ks < 2; ++ks) {
            const int kk = ks * 16;
            uint32_t ah[2][4], al[2][4];
            #pragma unroll
            for (int mt = 0; mt < 2; ++mt) {
                uint32_t ao = (uint32_t)((wm * 32 + mt * 16 + arow) * (PAK * 2) + (kk + ahalf * 8) * 2);
                LDSM4(ah[mt][0], ah[mt][1], ah[mt][2], ah[mt][3], uAh + ao);
                LDSM4(al[mt][0], al[mt][1], al[mt][2], al[mt][3], uAl + ao);
            }
            #pragma unroll
            for (int np = 0; np < 4; ++np) {
                uint32_t bo = (uint32_t)((wn * 64 + np * 16 + brow) * (PAK * 2) + (kk + bcol) * 2);
                uint32_t bh[4], bl[4];
                LDSM4(bh[0], bh[1], bh[2], bh[3], uBh + bo);
                LDSM4(bl[0], bl[1], bl[2], bl[3], uBl + bo);
                #pragma unroll
                for (int mt = 0; mt < 2; ++mt) {
                    MMA16816(c[mt][2 * np],     ah[mt], bh[0], bh[1]);
                    MMA16816(c[mt][2 * np + 1], ah[mt], bh[2], bh[3]);
                    MMA16816(c[mt][2 * np],     ah[mt], bl[0], bl[1]);
                    MMA16816(c[mt][2 * np + 1], ah[mt], bl[2], bl[3]);
                    MMA16816(c[mt][2 * np],     al[mt], bh[0], bh[1]);
                    MMA16816(c[mt][2 * np + 1], al[mt], bh[2], bh[3]);
                }
            }
        }
    }

    const int g  = lane >> 2;
    const int tg = lane & 3;
    float* base = g_xwb + (size_t)(m0 + wm * 32) * 1024 + n0 + wn * 64;
    #pragma unroll
    for (int mt = 0; mt < 2; ++mt) {
        #pragma unroll
        for (int nt = 0; nt < 8; ++nt) {
            float2 bv = *(float2*)&sBias[wn * 64 + nt * 8 + 2 * tg];
            float2 v0, v1;
            v0.x = c[mt][nt][0] + bv.x; v0.y = c[mt][nt][1] + bv.y;
            v1.x = c[mt][nt][2] + bv.x; v1.y = c[mt][nt][3] + bv.y;
            *(float2*)(base + (size_t)(mt * 16 + g)     * 1024 + nt * 8 + 2 * tg) = v0;
            *(float2*)(base + (size_t)(mt * 16 + g + 8) * 1024 + nt * 8 + 2 * tg) = v1;
        }
    }
}

// ---------------- init ----------------
__global__ void init_state() {
    int i = blockIdx.x * blockDim.x + threadIdx.x;
    if (i == 0) g_bar = 0u;
    if (i < 16 * 64) ((unsigned*)g_rbar)[i] = 0u;
    if (i < BSZ * HID / 4) ((uint4*)g_hpk[0])[i] = make_uint4(0u, 0u, 0u, 0u);
}

// ---------------- serial loop ----------------
// 128 CTAs = 16 row-groups(16 rows) x 8 col-CTAs(32 hcols, N=128 gate cols).
// 8 warps: warp w = n16 block w (gate-interleaved: n = w*16 + g*4 + q, hcol = w*4+q),
// m16 = all 16 rows, full K=256 per warp. Own output cols == one 32-k A chunk:
// stored locally via STS (no L2 round trip) and its MMA overlaps the barrier poll.
__global__ void __launch_bounds__(256, 1) lstm_serial(
    const int* __restrict__ lengths,
    const float* __restrict__ Wf, const float* __restrict__ Wi,
    const float* __restrict__ Wc, const float* __restrict__ Wo,
    const float* __restrict__ Wy, const float* __restrict__ by,
    float* __restrict__ out)
{
    char* sm = smem_dyn;
    const uint32_t uBase = s2u(sm);

    const int tid  = threadIdx.x;
    const int w    = tid >> 5;
    const int lane = tid & 31;
    const int bid  = blockIdx.x;
    const int grp  = bid >> 3;        // 16 groups of 16 rows
    const int colc = bid & 7;
    const int b0   = grp * 16;
    const int j0   = colc * 32;
    const int ckOwn = colc;           // own A k-chunk (32 cols)
    unsigned* myctr = &g_rbar[grp][0];

    // ---- zero both A buffers; stage W hi/lo gate-interleaved: n = w*16 + g*4 + q ----
    for (int i = tid; i < 2 * A_BUFSZ / 4; i += 256) ((uint32_t*)sm)[i] = 0u;
    for (int i = tid; i < 128 * 256; i += 256) {
        int n = i & 127, k = i >> 7;
        int wb = n >> 4, l = n & 15, g = l >> 2, q = l & 3;
        int j = j0 + wb * 4 + q;
        const float* __restrict__ Wg = (g == 0) ? Wf : (g == 1) ? Wi : (g == 2) ? Wc : Wo;
        float v = Wg[(size_t)(DIN + k) * HID + j];
        int ck = k >> 5, kk = k & 31;
        uint32_t off = (uint32_t)(S_WH + ck * 10240 + n * 80 + kk * 2);
        *(__nv_bfloat16*)(sm + off)                  = __float2bfloat16(v);
        *(__nv_bfloat16*)(sm + off + (S_WL - S_WH))  = __float2bfloat16(v - rebf(v));
    }
    __syncthreads();

    // lane cell ownership (after shuffle exchange)
    const int gl   = lane >> 2;
    const int tg   = lane & 3;
    const bool lowhalf = (tg < 2);
    const int rowL = gl + (lowhalf ? 0 : 8);      // 0..15
    const int rowG = b0 + rowL;
    const int jl   = w * 4 + 2 * (tg & 1);        // local col 0..31
    const int jg   = j0 + jl;
    const int len  = lengths[rowG];
    float2 cst = make_float2(0.f, 0.f);
    uint32_t hp0 = 0u, hp1 = 0u;

    // MMA fragment addressing
    const int arow  = lane & 15;
    const int ahalf = (lane >> 4) & 1;
    const int brow  = ((lane >> 4) & 1) * 8 + (lane & 7);
    const int bcol  = ((lane >> 3) & 1) * 8;

    // staging mapping: thread -> row (tid>>6 per it), fixed quad q = tid&63
    const int sq  = tid & 63;            // uint4 index within row (ck = sq>>3)
    const int sck = sq >> 3;
    const bool sSkip = (sck == ckOwn);
    const uint32_t sOff = (uint32_t)(sck * 1280 + (sq & 7) * 8);

    // xwb prefetch t=0
    const float* xr0 = g_xwb + ((size_t)rowG) * 1024 + jg;
    float2 pf = __ldcg((const float2*)xr0);
    float2 pi = __ldcg((const float2*)(xr0 + 256));
    float2 pc = __ldcg((const float2*)(xr0 + 512));
    float2 po = __ldcg((const float2*)(xr0 + 768));

    float c0[4] = {0.f, 0.f, 0.f, 0.f};   // carry own-chunk partial across barrier
    float c1[4] = {0.f, 0.f, 0.f, 0.f};

    for (int t = 0; t < TS; ++t) {
        const uint32_t aHi = uBase + (uint32_t)((t & 1) * A_BUFSZ);

        // ---- stage 7 non-own chunks from g_hpk[t&1] ----
        if (!sSkip) {
            const uint32_t* hprev = g_hpk[t & 1];
            #pragma unroll
            for (int it = 0; it < 4; ++it) {
                int r = (tid >> 6) + it * 4;
                uint4 p = __ldcg((const uint4*)(hprev + (size_t)(b0 + r) * HID + sq * 4));
                uint2 hi, lo;
                hi.x = __byte_perm(p.x, p.y, 0x7632);
                hi.y = __byte_perm(p.z, p.w, 0x7632);
                lo.x = __byte_perm(p.x, p.y, 0x5410);
                lo.y = __byte_perm(p.z, p.w, 0x5410);
                uint32_t off = (uint32_t)((t & 1) * A_BUFSZ) + sOff + (uint32_t)(r * 80);
                *(uint2*)(sm + off)        = hi;
                *(uint2*)(sm + off + A_LO) = lo;
            }
        }
        __syncthreads();

        // ---- MMA remaining 7 chunks (own chunk already in c0/c1) ----
        #pragma unroll
        for (int cc = 1; cc < 8; ++cc) {
            const int ck = (ckOwn + cc) & 7;
            #pragma unroll
            for (int ks = 0; ks < 2; ++ks) {
                const int kk = ks * 16;
                uint32_t ah[4], al[4], bh[4], bl[4];
                uint32_t ao = aHi + (uint32_t)(ck * 1280 + arow * 80 + (kk + ahalf * 8) * 2);
                LDSM4(ah[0], ah[1], ah[2], ah[3], ao);
                LDSM4(al[0], al[1], al[2], al[3], ao + A_LO);
                uint32_t bo = uBase + (uint32_t)(S_WH + ck * 10240 + (w * 16 + brow) * 80 + (kk + bcol) * 2);
                LDSM4(bh[0], bh[1], bh[2], bh[3], bo);
                LDSM4(bl[0], bl[1], bl[2], bl[3], bo + (S_WL - S_WH));
                MMA16816(c0, ah, bh[0], bh[1]);
                MMA16816(c1, ah, bh[2], bh[3]);
                MMA16816(c0, ah, bl[0], bl[1]);
                MMA16816(c1, ah, bl[2], bl[3]);
                MMA16816(c0, al, bh[0], bh[1]);
                MMA16816(c1, al, bh[2], bh[3]);
            }
        }

        // ---- warp-local gate exchange + epilogue + publish ----
        {
            float s0 = lowhalf ? c0[2] : c0[0];
            float s1 = lowhalf ? c0[3] : c0[1];
            float s2 = lowhalf ? c1[2] : c1[0];
            float s3 = lowhalf ? c1[3] : c1[1];
            float e0 = __shfl_xor_sync(0xffffffffu, s0, 2);
            float e1 = __shfl_xor_sync(0xffffffffu, s1, 2);
            float e2 = __shfl_xor_sync(0xffffffffu, s2, 2);
            float e3 = __shfl_xor_sync(0xffffffffu, s3, 2);

            float f0, f1, i0, i1, q0, q1, o0, o1;
            if (lowhalf) {
                f0 = c0[0]; f1 = c0[1]; q0 = c1[0]; q1 = c1[1];
                i0 = e0;    i1 = e1;    o0 = e2;    o1 = e3;
            } else {
                i0 = c0[2]; i1 = c0[3]; o0 = c1[2]; o1 = c1[3];
                f0 = e0;    f1 = e1;    q0 = e2;    q1 = e3;
            }

            float fg0 = sigmoidf_(f0 + pf.x), fg1 = sigmoidf_(f1 + pf.y);
            float ig0 = sigmoidf_(i0 + pi.x), ig1 = sigmoidf_(i1 + pi.y);
            float ch0 = tanhf_(q0 + pc.x),    ch1 = tanhf_(q1 + pc.y);
            float og0 = sigmoidf_(o0 + po.x), og1 = sigmoidf_(o1 + po.y);
            float cn0 = fg0 * cst.x + ig0 * ch0;
            float cn1 = fg1 * cst.y + ig1 * ch1;
            float hn0 = og0 * tanhf_(cn0);
            float hn1 = og1 * tanhf_(cn1);
            if (t < len) {
                cst.x = cn0; cst.y = cn1;
                hp0 = packsplit(hn0); hp1 = packsplit(hn1);
            }
            // publish to peers (packed-per-column format)
            uint2 hv; hv.x = hp0; hv.y = hp1;
            *(uint2*)(g_hpk[(t + 1) & 1] + (size_t)rowG * HID + jg) = hv;
            // store own chunk locally into next A buffer (plane-separated)
            uint32_t hiPair = __byte_perm(hp0, hp1, 0x7632);
            uint32_t loPair = __byte_perm(hp0, hp1, 0x5410);
            uint32_t so = (uint32_t)(((t + 1) & 1) * A_BUFSZ + ckOwn * 1280 + rowL * 80 + jl * 2);
            *(uint32_t*)(sm + so)        = hiPair;
            *(uint32_t*)(sm + so + A_LO) = loPair;
        }

        // ---- prefetch next xwb ----
        if (t + 1 < TS) {
            const float* xr = g_xwb + ((size_t)(t + 1) * BSZ + rowG) * 1024 + jg;
            pf = __ldcg((const float2*)xr);
            pi = __ldcg((const float2*)(xr + 256));
            pc = __ldcg((const float2*)(xr + 512));
            po = __ldcg((const float2*)(xr + 768));
        }

        __syncthreads();                     // STS + STG done CTA-wide
        if (tid == 0) arrive_release(myctr);

        // ---- own-chunk MMA for NEXT step (overlaps barrier poll) ----
        {
            #pragma unroll
            for (int q = 0; q < 4; ++q) { c0[q] = 0.f; c1[q] = 0.f; }
            const uint32_t aHiN = uBase + (uint32_t)(((t + 1) & 1) * A_BUFSZ);
            #pragma unroll
            for (int ks = 0; ks < 2; ++ks) {
                const int kk = ks * 16;
                uint32_t ah[4], al[4], bh[4], bl[4];
                uint32_t ao = aHiN + (uint32_t)(ckOwn * 1280 + arow * 80 + (kk + ahalf * 8) * 2);
                LDSM4(ah[0], ah[1], ah[2], ah[3], ao);
                LDSM4(al[0], al[1], al[2], al[3], ao + A_LO);
                uint32_t bo = uBase + (uint32_t)(S_WH + ckOwn * 10240 + (w * 16 + brow) * 80 + (kk + bcol) * 2);
                LDSM4(bh[0], bh[1], bh[2], bh[3], bo);
                LDSM4(bl[0], bl[1], bl[2], bl[3], bo + (S_WL - S_WH));
                MMA16816(c0, ah, bh[0], bh[1]);
                MMA16816(c1, ah, bh[2], bh[3]);
                MMA16816(c0, ah, bl[0], bl[1]);
                MMA16816(c1, ah, bl[2], bl[3]);
                MMA16816(c0, al, bh[0], bh[1]);
                MMA16816(c1, al, bh[2], bh[3]);
            }
        }

        if (tid == 0) wait_target(myctr, 8u * (unsigned)(t + 1));
        __syncthreads();
    }

    // global barrier before tail
    if (tid == 0) {
        arrive_release(&g_bar);
        wait_target(&g_bar, (unsigned)NCTA_S);
    }
    __syncthreads();

    // tail: y = h @ Wy + by (2 rows per CTA), then emit h (reconstructed fp32)
    const uint32_t* __restrict__ hfin = g_hpk[0];
    if (tid < 128) {
        const int row = bid * 2 + (tid >> 6);
        const int oc  = tid & 63;
        const uint32_t* hr = hfin + (size_t)row * HID;
        float acc = by[oc];
        #pragma unroll 4
        for (int k4 = 0; k4 < HID / 4; ++k4) {
            uint4 p = __ldcg((const uint4*)(hr + k4 * 4));
            const float* wp = Wy + (size_t)k4 * 4 * OUTD + oc;
            acc += unpacksplit(p.x) * wp[0] + unpacksplit(p.y) * wp[OUTD]
                 + unpacksplit(p.z) * wp[2 * OUTD] + unpacksplit(p.w) * wp[3 * OUTD];
        }
        out[(size_t)row * OUTD + oc] = acc;
    }
    {
        int idx = bid * 128 + tid;
        if (idx < BSZ * HID / 4 && tid < 128) {
            uint4 p = __ldcg(((const uint4*)hfin) + idx);
            float4 v;
            v.x = unpacksplit(p.x); v.y = unpacksplit(p.y);
            v.z = unpacksplit(p.z); v.w = unpacksplit(p.w);
            ((float4*)(out + BSZ * OUTD))[idx] = v;
        }
        idx = bid * 128 + 128 * NCTA_S + tid - 128;   // second half via tid>=128
        if (tid >= 128 && idx - 128 * NCTA_S + 128 * NCTA_S < BSZ * HID / 4) {
            int j = bid * 128 + (tid - 128) + NCTA_S * 128;
            if (j < BSZ * HID / 4) {
                uint4 p = __ldcg(((const uint4*)hfin) + j);
                float4 v;
                v.x = unpacksplit(p.x); v.y = unpacksplit(p.y);
                v.z = unpacksplit(p.z); v.w = unpacksplit(p.w);
                ((float4*)(out + BSZ * OUTD))[j] = v;
            }
        }
    }
}

extern "C" void kernel_launch(void* const* d_in, const int* in_sizes, int n_in,
                              void* d_out, int out_size) {
    const float* x       = (const float*)d_in[0];
    const int*   lengths = (const int*)  d_in[1];
    const float* Wf = (const float*)d_in[2];  const float* bf = (const float*)d_in[3];
    const float* Wi = (const float*)d_in[4];  const float* bi = (const float*)d_in[5];
    const float* Wc = (const float*)d_in[6];  const float* bc = (const float*)d_in[7];
    const float* Wo = (const float*)d_in[8];  const float* bo = (const float*)d_in[9];
    const float* Wy = (const float*)d_in[10]; const float* by = (const float*)d_in[11];
    float* out = (float*)d_out;

    cudaFuncSetAttribute(xw_mma, cudaFuncAttributeMaxDynamicSharedMemorySize, SMEM_MMA);
    cudaFuncSetAttribute(lstm_serial, cudaFuncAttributeMaxDynamicSharedMemorySize, SMEM_SER);

    convert_x<<<(MROWS * DIN / 4) / 256, 256>>>(x);
    convert_w<<<1024, 256>>>(Wf, Wi, Wc, Wo);
    xw_mma<<<dim3(8, MROWS / 128), 256, SMEM_MMA>>>(bf, bi, bc, bo);
    init_state<<<64, 256>>>();
    lstm_serial<<<NCTA_S, 256, SMEM_SER>>>(lengths, Wf, Wi, Wc, Wo, Wy, by, out);
}